// round 14
// baseline (speedup 1.0000x reference)
#include <cuda_runtime.h>
#include <math.h>

typedef unsigned long long ull;
constexpr int S_ = 500;

// ---------------- device scratch ----------------
__device__ float g_at2[1001 * 104];              // duplicated attn pairs
__device__ float g_c1[1001 * 100];
__device__ float g_ea[(size_t)4004 * 400];
__device__ float g_w2e[56 * 100];                // [W2(50); Wo@W2(4); colmean W2(1); 0]
__device__ float g_b2e[56];
__device__ float g_w1p[100 * 200];               // W1[:, :200] packed
__device__ float g_h[(size_t)512 * 500 * 200];   // read vectors

// ---------------- f32x2 helpers ----------------
#define FMA2(d, a, b, c) \
    asm("fma.rn.f32x2 %0, %1, %2, %3;" : "=l"(d) : "l"(a), "l"(b), "l"(c))
__device__ __forceinline__ ull PK(float x, float y) {
    ull u;
    asm("mov.b64 %0, {%1, %2};" : "=l"(u) : "r"(__float_as_uint(x)), "r"(__float_as_uint(y)));
    return u;
}
__device__ __forceinline__ float HADD(ull u) {
    unsigned lo, hi;
    asm("mov.b64 {%0, %1}, %2;" : "=r"(lo), "=r"(hi) : "l"(u));
    return __uint_as_float(lo) + __uint_as_float(hi);
}
__device__ __forceinline__ void UNPK(float& x, float& y, ull u) {
    unsigned lo, hi;
    asm("mov.b64 {%0, %1}, %2;" : "=r"(lo), "=r"(hi) : "l"(u));
    x = __uint_as_float(lo); y = __uint_as_float(hi);
}
__device__ __forceinline__ void cp16(float* dst, const float* src) {
    unsigned d = (unsigned)__cvta_generic_to_shared(dst);
    asm volatile("cp.async.ca.shared.global [%0], [%1], 16;\n" :: "r"(d), "l"(src));
}

// ================= prepBF: attn(+tk) | c1 | fold | w1 pack =================
__global__ void prepBF(const float* __restrict__ qet, const float* __restrict__ Wq,
                       const float* __restrict__ bq,
                       const float* __restrict__ km, const float* __restrict__ Wk,
                       const float* __restrict__ bk,
                       const float* __restrict__ W1, const float* __restrict__ b1,
                       const float* __restrict__ W2, const float* __restrict__ b2,
                       const float* __restrict__ Wo, const float* __restrict__ bo) {
    __shared__ float stk[2500], qe[50], qu[50], lg[50], red[2];
    int b = blockIdx.x, tid = threadIdx.x;
    if (b < 1001) {
        int q = b;
        for (int i = tid; i < 2500; i += 256) {
            int m = i / 50, k = i % 50;
            float a = bk[m];
            for (int l = 0; l < 50; l++) a = fmaf(km[l * 50 + k], Wk[m * 50 + l], a);
            stk[i] = a;
        }
        if (tid < 50) qe[tid] = qet[q * 50 + tid];
        __syncthreads();
        if (tid < 50) {
            float a = bq[tid];
            for (int l = 0; l < 50; l++) a = fmaf(Wq[tid * 50 + l], qe[l], a);
            qu[tid] = tanhf(a);
        }
        __syncthreads();
        if (tid < 50) {
            float a = 0.f;
            for (int k = 0; k < 50; k++) a = fmaf(stk[tid * 50 + k], qu[k], a);
            lg[tid] = a;
        }
        __syncthreads();
        if (tid == 0) {
            float mx = -1e30f;
            for (int m = 0; m < 50; m++) mx = fmaxf(mx, lg[m]);
            float s = 0.f;
            for (int m = 0; m < 50; m++) s += expf(lg[m] - mx);
            red[0] = mx; red[1] = 1.f / s;
        }
        __syncthreads();
        if (tid < 52) {
            float v = (tid < 50) ? expf(lg[tid] - red[0]) * red[1] : 0.f;
            g_at2[q * 104 + 2 * tid]     = v;
            g_at2[q * 104 + 2 * tid + 1] = v;
        }
    } else if (b < 1393) {
        int idx = (b - 1001) * 256 + tid;
        if (idx < 1001 * 100) {
            int q = idx / 100, j = idx % 100;
            float a = b1[j];
            const float* w = W1 + j * 250 + 200;
            const float* e = qet + q * 50;
            for (int k = 0; k < 50; k++) a = fmaf(w[k], e[k], a);
            g_c1[idx] = a;
        }
    } else if (b < 1416) {
        int i = (b - 1393) * 256 + tid;
        if (i < 5000) {
            g_w2e[i] = W2[i];
        } else if (i < 5400) {
            int idx = i - 5000, c = idx / 100, k = idx % 100;
            float a = 0.f;
            for (int f = 0; f < 50; f++) a = fmaf(Wo[c * 50 + f], W2[f * 100 + k], a);
            g_w2e[i] = a;
        } else if (i < 5500) {
            int k = i - 5400;
            float a = 0.f;
            for (int f = 0; f < 50; f++) a += W2[f * 100 + k];
            g_w2e[i] = a * (1.f / 50.f);
        } else if (i < 5600) {
            g_w2e[i] = 0.f;
        } else if (i < 5656) {
            int j = i - 5600;
            float v = 0.f;
            if (j < 50) v = b2[j];
            else if (j < 54) {
                int c = j - 50;
                v = bo[c];
                for (int f = 0; f < 50; f++) v = fmaf(Wo[c * 50 + f], b2[f], v);
            } else if (j == 54) {
                float a = 0.f;
                for (int f = 0; f < 50; f++) a += b2[f];
                v = a * (1.f / 50.f);
            }
            g_b2e[j] = v;
        }
    } else {
        int i = (b - 1416) * 256 + tid;
        if (i < 100 * 200) {
            int r = i / 200, c = i % 200;
            g_w1p[i] = W1[r * 250 + c];
        }
    }
}

// ================= prepC: erase/add GEMM, ve inline =================
__global__ void prepC(const float* __restrict__ We, const float* __restrict__ be,
                      const float* __restrict__ Wa, const float* __restrict__ ba,
                      const float* __restrict__ Wv, const float* __restrict__ bv) {
    __shared__ float As[16][64];
    __shared__ float Bs[16][64];
    int i0 = blockIdx.x * 64, j0 = blockIdx.y * 64;
    int tid = threadIdx.x;
    int ty = tid >> 4, tx = tid & 15;
    float acc[4][4] = {};
    for (int kb = 0; kb < 200; kb += 16) {
        for (int l = tid; l < 1024; l += 256) {
            {
                int c = l >> 6, r = l & 63;
                int gi = i0 + r, gk = kb + c;
                float val = 0.f;
                if (gi < 4004 && gk < 200) {
                    int q = gi >> 2, rr = gi & 3;
                    val = bv[gk];
                    if (q > 0) {
#pragma unroll
                        for (int cc = 0; cc < 4; cc++) {
                            float w = 1.0f - fabsf((float)(cc - rr)) * (1.0f / 3.0f);
                            if (w > 0.0f)
                                val = fmaf(w, Wv[gk * 4000 + cc * 1000 + q - 1], val);
                        }
                    }
                }
                As[c][r] = val;
            }
            {
                int r = l >> 4, c = l & 15;
                int gj = j0 + r, gk = kb + c;
                float bval = 0.f;
                if (gj < 400 && gk < 200)
                    bval = (gj < 200) ? We[gj * 200 + gk] : Wa[(gj - 200) * 200 + gk];
                Bs[c][r] = bval;
            }
        }
        __syncthreads();
#pragma unroll
        for (int k = 0; k < 16; k++) {
            float a[4], bb[4];
#pragma unroll
            for (int u = 0; u < 4; u++) a[u] = As[k][ty * 4 + u];
#pragma unroll
            for (int u = 0; u < 4; u++) bb[u] = Bs[k][tx * 4 + u];
#pragma unroll
            for (int u = 0; u < 4; u++)
#pragma unroll
                for (int v = 0; v < 4; v++) acc[u][v] = fmaf(a[u], bb[v], acc[u][v]);
        }
        __syncthreads();
    }
#pragma unroll
    for (int u = 0; u < 4; u++) {
        int gi = i0 + ty * 4 + u;
        if (gi >= 4004) break;
#pragma unroll
        for (int v = 0; v < 4; v++) {
            int gj = j0 + tx * 4 + v;
            if (gj >= 400) continue;
            float x = acc[u][v] + ((gj < 200) ? be[gj] : ba[gj - 200]);
            g_ea[(size_t)gi * 400 + gj] = (gj < 200) ? (1.0f / (1.0f + expf(-x))) : tanhf(x);
        }
    }
}

// ============ Phase 1: barrier-free, m-split (vm[25]/thread), occ 2 =========
#define TPB1 416
constexpr int G1 = 2;
constexpr int P1_SMF = 2000 + 13 * 416;   // 7408 floats

__global__ void __launch_bounds__(TPB1, 2)
phase1(const int* __restrict__ questions, const int* __restrict__ responses,
       const float* __restrict__ ivm) {
    __shared__ float sm[P1_SMF];
    int* qs = (int*)sm;
    int* rs = (int*)(sm + 1000);
    const int tid = threadIdx.x;
    const int wid = tid >> 5, lane = tid & 31;
    const int b0 = blockIdx.x * G1;

    for (int i = tid; i < G1 * S_; i += TPB1) {
        qs[i] = questions[b0 * S_ + i];
        rs[i] = responses[b0 * S_ + i];
    }

    const int cp = (tid < 400) ? tid : 399;
    const int pp = cp >> 1;           // v-pair index 0..199
    const int mh = cp & 1;            // m-half
    const int g = pp / 100, p = pp % 100;
    const int wg0 = (wid * 16) / 100;
    const int wg1 = min(G1 - 1, (wid * 16 + 15) / 100);
    const int myslot = (g > wg0) ? 1 : 0;

    ull vm[25];
#pragma unroll
    for (int j = 0; j < 25; j++)
        vm[j] = *(const ull*)(ivm + (mh * 25 + j) * 200 + 2 * p);

    __syncthreads();   // only block barrier (qs/rs visible)

    float* mybuf = sm + 2000 + wid * 416;   // [buf d][slot s][104]
    const int* qsg = qs + g * S_;
    const int* rsg = rs + g * S_;

    // prologue: attn(0) — 52 x 16B chunks cover both 416B slots fully
    for (int i = lane; i < 52; i += 32) {
        int s = i / 26, j = i % 26;
        int qq = qs[(s ? wg1 : wg0) * S_];
        cp16(mybuf + s * 104 + j * 4, g_at2 + qq * 104 + j * 4);
    }
    asm volatile("cp.async.commit_group;\n" ::: "memory");

    ull eC, aC;
    {
        const float* eb = g_ea + (size_t)(qsg[0] * 4 + rsg[0]) * 400;
        eC = *(const ull*)(eb + 2 * p);
        aC = *(const ull*)(eb + 200 + 2 * p);
    }

    size_t hb = (size_t)(b0 + g) * (S_ * 200) + 2 * p + mh;

    for (int t = 0; t < S_; t++) {
        ull eN = 0ull, aN = 0ull;
        if (t + 1 < S_) {
            const float* eb = g_ea + (size_t)(qsg[t + 1] * 4 + rsg[t + 1]) * 400;
            eN = *(const ull*)(eb + 2 * p);
            aN = *(const ull*)(eb + 200 + 2 * p);
            float* nb = mybuf + ((t + 1) & 1) * 208;
            for (int i = lane; i < 52; i += 32) {
                int s = i / 26, j = i % 26;
                int qq = qs[(s ? wg1 : wg0) * S_ + t + 1];
                cp16(nb + s * 104 + j * 4, g_at2 + qq * 104 + j * 4);
            }
        }
        asm volatile("cp.async.commit_group;\n" ::: "memory");
        asm volatile("cp.async.wait_group 1;\n" ::: "memory");
        __syncwarp();

        // my half of the attn pairs (ull index mh*25 + j)
        const ull* at2p = (const ull*)(mybuf + (t & 1) * 208 + myslot * 104) + mh * 25;
        ull en = eC ^ 0x8000000080000000ULL;
        ull ad = aC;
        ull ra = 0ull, rb = 0ull;
#pragma unroll
        for (int j = 0; j < 25; j++) {
            ull a = at2p[j];
            ull tt;
            if (j & 1) FMA2(rb, a, vm[j], rb);
            else       FMA2(ra, a, vm[j], ra);
            FMA2(tt, en, vm[j], ad);
            FMA2(vm[j], a, tt, vm[j]);
        }
        ull one2 = PK(1.0f, 1.0f), r2;
        FMA2(r2, rb, one2, ra);
        float rx, ry;
        UNPK(rx, ry, r2);
        rx += __shfl_xor_sync(0xffffffffu, rx, 1);   // combine m-halves
        ry += __shfl_xor_sync(0xffffffffu, ry, 1);
        if (tid < 400)
            g_h[hb + (size_t)t * 200] = (mh == 0) ? rx : ry;   // coalesced 4B/lane
        eC = eN; aC = aN;
    }
}

// ================= Phase 2: batched MLP (R12, unchanged) =================
#define TPB2 256
constexpr int R2 = 64;
constexpr int HSTR = 204;
constexpr int H1STR = 108;
constexpr int O2_H   = 0;
constexpr int O2_H1  = 13056;
constexpr int O2_W2E = 19968;
constexpr int O2_B2E = 25568;
constexpr int O2_LG  = 25624;
constexpr int O2_QN  = 25880;
constexpr int P2_SMF = 25944;

__global__ void __launch_bounds__(TPB2, 2)
phase2(const int* __restrict__ questions,
       float* __restrict__ outF, float* __restrict__ outM,
       float* __restrict__ outL, float* __restrict__ outP) {
    extern __shared__ float s2[];
    const int tid = threadIdx.x;
    const int n0 = blockIdx.x * R2;
    int* qn = (int*)(s2 + O2_QN);

    for (int i = tid; i < 3200; i += TPB2) {
        int r = i / 50, c = i % 50;
        cp16(s2 + O2_H + r * HSTR + c * 4, g_h + (size_t)(n0 + r) * 200 + c * 4);
    }
    for (int i = tid; i < 1400; i += TPB2)
        cp16(s2 + O2_W2E + i * 4, g_w2e + i * 4);
    if (tid < 14) cp16(s2 + O2_B2E + tid * 4, g_b2e + tid * 4);
    if (tid < R2) qn[tid] = questions[n0 + tid];
    asm volatile("cp.async.commit_group;\n" ::: "memory");
    asm volatile("cp.async.wait_group 0;\n" ::: "memory");
    __syncthreads();

    if (tid < 200) {
        int jg = tid / 8, rg = tid % 8;
        int j0 = jg * 4;
        ull acc[4][8] = {};
        for (int k = 0; k < 200; k += 4) {
            ulonglong2 h[8];
#pragma unroll
            for (int i = 0; i < 8; i++)
                h[i] = *(const ulonglong2*)(s2 + O2_H + (rg + 8 * i) * HSTR + k);
#pragma unroll
            for (int j = 0; j < 4; j++) {
                ulonglong2 w = *(const ulonglong2*)(g_w1p + (j0 + j) * 200 + k);
#pragma unroll
                for (int i = 0; i < 8; i++) {
                    FMA2(acc[j][i], w.x, h[i].x, acc[j][i]);
                    FMA2(acc[j][i], w.y, h[i].y, acc[j][i]);
                }
            }
        }
#pragma unroll
        for (int j = 0; j < 4; j++)
#pragma unroll
            for (int i = 0; i < 8; i++) {
                int row = rg + 8 * i;
                float v = HADD(acc[j][i]) + g_c1[qn[row] * 100 + j0 + j];
                s2[O2_H1 + row * H1STR + j0 + j] = fmaxf(v, 0.f);
            }
    }
    __syncthreads();

    if (tid < 224) {
        int fg = tid >> 3, rg = tid & 7;
        int f0 = fg * 2;
        ull acc[2][8] = {};
        for (int k = 0; k < 100; k += 4) {
            ulonglong2 h1v[8];
#pragma unroll
            for (int i = 0; i < 8; i++)
                h1v[i] = *(const ulonglong2*)(s2 + O2_H1 + (rg + 8 * i) * H1STR + k);
#pragma unroll
            for (int j = 0; j < 2; j++) {
                ull w0 = *(const ull*)(s2 + O2_W2E + (f0 + j) * 100 + k);
                ull w1 = *(const ull*)(s2 + O2_W2E + (f0 + j) * 100 + k + 2);
#pragma unroll
                for (int i = 0; i < 8; i++) {
                    FMA2(acc[j][i], w0, h1v[i].x, acc[j][i]);
                    FMA2(acc[j][i], w1, h1v[i].y, acc[j][i]);
                }
            }
        }
#pragma unroll
        for (int j = 0; j < 2; j++) {
            int f = f0 + j;
            if (f >= 55) continue;
            float bias = s2[O2_B2E + f];
#pragma unroll
            for (int i = 0; i < 8; i++) {
                int row = rg + 8 * i;
                float val = HADD(acc[j][i]) + bias;
                if (f < 50)      outF[(size_t)(n0 + row) * 50 + f] = val;
                else if (f < 54) s2[O2_LG + row * 4 + (f - 50)] = val;
                else             outM[n0 + row] = val;
            }
        }
    }
    __syncthreads();

    {
        int row = tid >> 2, c = tid & 3;
        float lg = s2[O2_LG + row * 4 + c];
        float mx = fmaxf(lg, __shfl_xor_sync(0xffffffffu, lg, 1));
        mx = fmaxf(mx, __shfl_xor_sync(0xffffffffu, mx, 2));
        float e = expf(lg - mx);
        float se = e + __shfl_xor_sync(0xffffffffu, e, 1);
        se += __shfl_xor_sync(0xffffffffu, se, 2);
        size_t o = (size_t)(n0 + row) * 4 + c;
        outL[o] = lg;
        outP[o] = e / se;
    }
}

// ---------------------------------------------------------------------------

extern "C" void kernel_launch(void* const* d_in, const int* in_sizes, int n_in,
                              void* d_out, int out_size) {
    const int*   questions = (const int*)d_in[0];
    const int*   responses = (const int*)d_in[1];
    const float* qet       = (const float*)d_in[2];
    const float* Wv        = (const float*)d_in[3];
    const float* bv        = (const float*)d_in[4];
    const float* km        = (const float*)d_in[5];
    const float* ivm       = (const float*)d_in[6];
    const float* Wq        = (const float*)d_in[7];
    const float* bq        = (const float*)d_in[8];
    const float* Wk        = (const float*)d_in[9];
    const float* bk        = (const float*)d_in[10];
    const float* We        = (const float*)d_in[11];
    const float* be        = (const float*)d_in[12];
    const float* Wa        = (const float*)d_in[13];
    const float* ba        = (const float*)d_in[14];
    const float* W1        = (const float*)d_in[15];
    const float* b1        = (const float*)d_in[16];
    const float* W2        = (const float*)d_in[17];
    const float* b2        = (const float*)d_in[18];
    const float* Wo        = (const float*)d_in[19];
    const float* bo        = (const float*)d_in[20];

    float* out  = (float*)d_out;
    float* outF = out;
    float* outM = out + (size_t)512 * 500 * 50;
    float* outL = outM + (size_t)512 * 500;
    float* outP = outL + (size_t)512 * 500 * 4;

    cudaFuncSetAttribute(phase2, cudaFuncAttributeMaxDynamicSharedMemorySize,
                         P2_SMF * 4);

    prepBF<<<1495, 256>>>(qet, Wq, bq, km, Wk, bk, W1, b1, W2, b2, Wo, bo);
    {
        dim3 grid(63, 7);
        prepC<<<grid, 256>>>(We, be, Wa, ba, Wv, bv);
    }
    phase1<<<512 / G1, TPB1>>>(questions, responses, ivm);
    phase2<<<512 * 500 / R2, TPB2, P2_SMF * 4>>>(questions,
                                                 outF, outM, outL, outP);
}

// round 15
// speedup vs baseline: 1.0146x; 1.0146x over previous
#include <cuda_runtime.h>
#include <math.h>

typedef unsigned long long ull;
constexpr int S_ = 500;

// ---------------- device scratch ----------------
__device__ float g_at2[1001 * 104];              // duplicated attn pairs
__device__ float g_c1[1001 * 100];
__device__ float g_ea[(size_t)4004 * 400];
__device__ float g_w2e[56 * 100];                // [W2(50); Wo@W2(4); colmean W2(1); 0]
__device__ float g_b2e[56];
__device__ float g_w1p[100 * 200];               // W1[:, :200] packed
__device__ float g_h[(size_t)512 * 500 * 200];   // read vectors

// ---------------- f32x2 helpers ----------------
#define FMA2(d, a, b, c) \
    asm("fma.rn.f32x2 %0, %1, %2, %3;" : "=l"(d) : "l"(a), "l"(b), "l"(c))
__device__ __forceinline__ ull PK(float x, float y) {
    ull u;
    asm("mov.b64 %0, {%1, %2};" : "=l"(u) : "r"(__float_as_uint(x)), "r"(__float_as_uint(y)));
    return u;
}
__device__ __forceinline__ float HADD(ull u) {
    unsigned lo, hi;
    asm("mov.b64 {%0, %1}, %2;" : "=r"(lo), "=r"(hi) : "l"(u));
    return __uint_as_float(lo) + __uint_as_float(hi);
}
__device__ __forceinline__ void cp16(float* dst, const float* src) {
    unsigned d = (unsigned)__cvta_generic_to_shared(dst);
    asm volatile("cp.async.ca.shared.global [%0], [%1], 16;\n" :: "r"(d), "l"(src));
}

// ================= prepBF: attn(+tk) | c1 | fold | w1 pack =================
__global__ void prepBF(const float* __restrict__ qet, const float* __restrict__ Wq,
                       const float* __restrict__ bq,
                       const float* __restrict__ km, const float* __restrict__ Wk,
                       const float* __restrict__ bk,
                       const float* __restrict__ W1, const float* __restrict__ b1,
                       const float* __restrict__ W2, const float* __restrict__ b2,
                       const float* __restrict__ Wo, const float* __restrict__ bo) {
    __shared__ float stk[2500], qe[50], qu[50], lg[50], red[2];
    int b = blockIdx.x, tid = threadIdx.x;
    if (b < 1001) {
        int q = b;
        for (int i = tid; i < 2500; i += 256) {
            int m = i / 50, k = i % 50;
            float a = bk[m];
            for (int l = 0; l < 50; l++) a = fmaf(km[l * 50 + k], Wk[m * 50 + l], a);
            stk[i] = a;
        }
        if (tid < 50) qe[tid] = qet[q * 50 + tid];
        __syncthreads();
        if (tid < 50) {
            float a = bq[tid];
            for (int l = 0; l < 50; l++) a = fmaf(Wq[tid * 50 + l], qe[l], a);
            qu[tid] = tanhf(a);
        }
        __syncthreads();
        if (tid < 50) {
            float a = 0.f;
            for (int k = 0; k < 50; k++) a = fmaf(stk[tid * 50 + k], qu[k], a);
            lg[tid] = a;
        }
        __syncthreads();
        if (tid == 0) {
            float mx = -1e30f;
            for (int m = 0; m < 50; m++) mx = fmaxf(mx, lg[m]);
            float s = 0.f;
            for (int m = 0; m < 50; m++) s += expf(lg[m] - mx);
            red[0] = mx; red[1] = 1.f / s;
        }
        __syncthreads();
        if (tid < 52) {
            float v = (tid < 50) ? expf(lg[tid] - red[0]) * red[1] : 0.f;
            g_at2[q * 104 + 2 * tid]     = v;
            g_at2[q * 104 + 2 * tid + 1] = v;
        }
    } else if (b < 1393) {
        int idx = (b - 1001) * 256 + tid;
        if (idx < 1001 * 100) {
            int q = idx / 100, j = idx % 100;
            float a = b1[j];
            const float* w = W1 + j * 250 + 200;
            const float* e = qet + q * 50;
            for (int k = 0; k < 50; k++) a = fmaf(w[k], e[k], a);
            g_c1[idx] = a;
        }
    } else if (b < 1416) {
        int i = (b - 1393) * 256 + tid;
        if (i < 5000) {
            g_w2e[i] = W2[i];
        } else if (i < 5400) {
            int idx = i - 5000, c = idx / 100, k = idx % 100;
            float a = 0.f;
            for (int f = 0; f < 50; f++) a = fmaf(Wo[c * 50 + f], W2[f * 100 + k], a);
            g_w2e[i] = a;
        } else if (i < 5500) {
            int k = i - 5400;
            float a = 0.f;
            for (int f = 0; f < 50; f++) a += W2[f * 100 + k];
            g_w2e[i] = a * (1.f / 50.f);
        } else if (i < 5600) {
            g_w2e[i] = 0.f;
        } else if (i < 5656) {
            int j = i - 5600;
            float v = 0.f;
            if (j < 50) v = b2[j];
            else if (j < 54) {
                int c = j - 50;
                v = bo[c];
                for (int f = 0; f < 50; f++) v = fmaf(Wo[c * 50 + f], b2[f], v);
            } else if (j == 54) {
                float a = 0.f;
                for (int f = 0; f < 50; f++) a += b2[f];
                v = a * (1.f / 50.f);
            }
            g_b2e[j] = v;
        }
    } else {
        int i = (b - 1416) * 256 + tid;
        if (i < 100 * 200) {
            int r = i / 200, c = i % 200;
            g_w1p[i] = W1[r * 250 + c];
        }
    }
}

// ================= prepC: erase/add GEMM, ve inline =================
__global__ void prepC(const float* __restrict__ We, const float* __restrict__ be,
                      const float* __restrict__ Wa, const float* __restrict__ ba,
                      const float* __restrict__ Wv, const float* __restrict__ bv) {
    __shared__ float As[16][64];
    __shared__ float Bs[16][64];
    int i0 = blockIdx.x * 64, j0 = blockIdx.y * 64;
    int tid = threadIdx.x;
    int ty = tid >> 4, tx = tid & 15;
    float acc[4][4] = {};
    for (int kb = 0; kb < 200; kb += 16) {
        for (int l = tid; l < 1024; l += 256) {
            {
                int c = l >> 6, r = l & 63;
                int gi = i0 + r, gk = kb + c;
                float val = 0.f;
                if (gi < 4004 && gk < 200) {
                    int q = gi >> 2, rr = gi & 3;
                    val = bv[gk];
                    if (q > 0) {
#pragma unroll
                        for (int cc = 0; cc < 4; cc++) {
                            float w = 1.0f - fabsf((float)(cc - rr)) * (1.0f / 3.0f);
                            if (w > 0.0f)
                                val = fmaf(w, Wv[gk * 4000 + cc * 1000 + q - 1], val);
                        }
                    }
                }
                As[c][r] = val;
            }
            {
                int r = l >> 4, c = l & 15;
                int gj = j0 + r, gk = kb + c;
                float bval = 0.f;
                if (gj < 400 && gk < 200)
                    bval = (gj < 200) ? We[gj * 200 + gk] : Wa[(gj - 200) * 200 + gk];
                Bs[c][r] = bval;
            }
        }
        __syncthreads();
#pragma unroll
        for (int k = 0; k < 16; k++) {
            float a[4], bb[4];
#pragma unroll
            for (int u = 0; u < 4; u++) a[u] = As[k][ty * 4 + u];
#pragma unroll
            for (int u = 0; u < 4; u++) bb[u] = Bs[k][tx * 4 + u];
#pragma unroll
            for (int u = 0; u < 4; u++)
#pragma unroll
                for (int v = 0; v < 4; v++) acc[u][v] = fmaf(a[u], bb[v], acc[u][v]);
        }
        __syncthreads();
    }
#pragma unroll
    for (int u = 0; u < 4; u++) {
        int gi = i0 + ty * 4 + u;
        if (gi >= 4004) break;
#pragma unroll
        for (int v = 0; v < 4; v++) {
            int gj = j0 + tx * 4 + v;
            if (gj >= 400) continue;
            float x = acc[u][v] + ((gj < 200) ? be[gj] : ba[gj - 200]);
            g_ea[(size_t)gi * 400 + gj] = (gj < 200) ? (1.0f / (1.0f + expf(-x))) : tanhf(x);
        }
    }
}

// ======== Phase 1: barrier-free Vm recurrence, G1=4 (R12, frozen) ========
#define TPB1 416
constexpr int G1 = 4;
constexpr int P1_SMF = 4000 + 13 * 416;

__global__ void __launch_bounds__(TPB1, 1)
phase1(const int* __restrict__ questions, const int* __restrict__ responses,
       const float* __restrict__ ivm) {
    __shared__ float sm[P1_SMF];
    int* qs = (int*)sm;
    int* rs = (int*)(sm + 2000);
    const int tid = threadIdx.x;
    const int wid = tid >> 5, lane = tid & 31;
    const int b0 = blockIdx.x * G1;

    for (int i = tid; i < G1 * S_; i += TPB1) {
        qs[i] = questions[b0 * S_ + i];
        rs[i] = responses[b0 * S_ + i];
    }

    const int cp = (tid < 400) ? tid : 399;
    const int g = cp / 100, p = cp % 100;
    const int wg0 = (wid * 32) / 100;
    const int wg1 = min(3, (wid * 32 + 31) / 100);
    const int myslot = (g > wg0) ? 1 : 0;

    ull vm[50];
#pragma unroll
    for (int m = 0; m < 50; m++) vm[m] = *(const ull*)(ivm + m * 200 + 2 * p);

    __syncthreads();

    float* mybuf = sm + 4000 + wid * 416;
    const int* qsg = qs + g * S_;
    const int* rsg = rs + g * S_;

    for (int i = lane; i < 52; i += 32) {
        int s = i / 26, j = i % 26;
        int qq = qs[(s ? wg1 : wg0) * S_];
        cp16(mybuf + s * 104 + j * 4, g_at2 + qq * 104 + j * 4);
    }
    asm volatile("cp.async.commit_group;\n" ::: "memory");

    ull eC, aC;
    {
        const float* eb = g_ea + (size_t)(qsg[0] * 4 + rsg[0]) * 400;
        eC = *(const ull*)(eb + 2 * p);
        aC = *(const ull*)(eb + 200 + 2 * p);
    }

    size_t hb = (size_t)(b0 + g) * (S_ * 200) + 2 * p;

    for (int t = 0; t < S_; t++) {
        ull eN = 0ull, aN = 0ull;
        if (t + 1 < S_) {
            const float* eb = g_ea + (size_t)(qsg[t + 1] * 4 + rsg[t + 1]) * 400;
            eN = *(const ull*)(eb + 2 * p);
            aN = *(const ull*)(eb + 200 + 2 * p);
            float* nb = mybuf + ((t + 1) & 1) * 208;
            for (int i = lane; i < 52; i += 32) {
                int s = i / 26, j = i % 26;
                int qq = qs[(s ? wg1 : wg0) * S_ + t + 1];
                cp16(nb + s * 104 + j * 4, g_at2 + qq * 104 + j * 4);
            }
        }
        asm volatile("cp.async.commit_group;\n" ::: "memory");
        asm volatile("cp.async.wait_group 1;\n" ::: "memory");
        __syncwarp();

        const ulonglong2* at2p =
            (const ulonglong2*)(mybuf + (t & 1) * 208 + myslot * 104);
        ull en = eC ^ 0x8000000080000000ULL;
        ull ad = aC;
        ull ra = 0ull, rb = 0ull;
#pragma unroll
        for (int j2 = 0; j2 < 25; j2++) {
            ulonglong2 uu = at2p[j2];
            ull tt;
            FMA2(ra, uu.x, vm[2 * j2], ra);
            FMA2(tt, en, vm[2 * j2], ad);
            FMA2(vm[2 * j2], uu.x, tt, vm[2 * j2]);
            FMA2(rb, uu.y, vm[2 * j2 + 1], rb);
            FMA2(tt, en, vm[2 * j2 + 1], ad);
            FMA2(vm[2 * j2 + 1], uu.y, tt, vm[2 * j2 + 1]);
        }
        ull one2 = PK(1.0f, 1.0f), r2;
        FMA2(r2, rb, one2, ra);
        if (tid < 400)
            *(ull*)(g_h + hb + (size_t)t * 200) = r2;
        eC = eN; aC = aN;
    }
}

// ====== Phase 2: batched MLP, 4 tiles of 64 rows/block, pipelined h ======
#define TPB2 256
constexpr int NT = 4;            // tiles per block
constexpr int R2 = 64;
constexpr int HSTR = 204;
constexpr int H1STR = 108;
constexpr int O2_H   = 0;               // 64 x 204 = 13056
constexpr int O2_H1  = 13056;           // 64 x 108 = 6912
constexpr int O2_W2E = 19968;           // 5600
constexpr int O2_B2E = 25568;           // 56
constexpr int O2_LG  = 25624;           // 256
constexpr int O2_QN  = 25880;           // 2 x 64 int
constexpr int P2_SMF = 26008;           // 104,032 B

__global__ void __launch_bounds__(TPB2, 2)
phase2(const int* __restrict__ questions,
       float* __restrict__ outF, float* __restrict__ outM,
       float* __restrict__ outL, float* __restrict__ outP) {
    extern __shared__ float s2[];
    const int tid = threadIdx.x;
    const int nb = blockIdx.x * (NT * R2);
    int* qn = (int*)(s2 + O2_QN);

    // ---- prologue: W2e, b2e, h(tile 0), qn(tile 0) ----
    for (int i = tid; i < 1400; i += TPB2)
        cp16(s2 + O2_W2E + i * 4, g_w2e + i * 4);
    if (tid < 14) cp16(s2 + O2_B2E + tid * 4, g_b2e + tid * 4);
    for (int i = tid; i < 3200; i += TPB2) {
        int r = i / 50, c = i % 50;
        cp16(s2 + O2_H + r * HSTR + c * 4, g_h + (size_t)(nb + r) * 200 + c * 4);
    }
    if (tid < R2) qn[tid] = questions[nb + tid];
    asm volatile("cp.async.commit_group;\n" ::: "memory");

    for (int it = 0; it < NT; it++) {
        const int n0 = nb + it * R2;
        asm volatile("cp.async.wait_group 0;\n" ::: "memory");
        __syncthreads();
        const int* qc = qn + (it & 1) * R2;

        // ---- stage B: h1 = relu(W1p @ h + c1[q]) ----
        if (tid < 200) {
            int jg = tid / 8, rg = tid % 8;
            int j0 = jg * 4;
            ull acc[4][8] = {};
            for (int k = 0; k < 200; k += 4) {
                ulonglong2 h[8];
#pragma unroll
                for (int i = 0; i < 8; i++)
                    h[i] = *(const ulonglong2*)(s2 + O2_H + (rg + 8 * i) * HSTR + k);
#pragma unroll
                for (int j = 0; j < 4; j++) {
                    ulonglong2 w = *(const ulonglong2*)(g_w1p + (j0 + j) * 200 + k);
#pragma unroll
                    for (int i = 0; i < 8; i++) {
                        FMA2(acc[j][i], w.x, h[i].x, acc[j][i]);
                        FMA2(acc[j][i], w.y, h[i].y, acc[j][i]);
                    }
                }
            }
#pragma unroll
            for (int j = 0; j < 4; j++)
#pragma unroll
                for (int i = 0; i < 8; i++) {
                    int row = rg + 8 * i;
                    float v = HADD(acc[j][i]) + g_c1[qc[row] * 100 + j0 + j];
                    s2[O2_H1 + row * H1STR + j0 + j] = fmaxf(v, 0.f);
                }
        }
        __syncthreads();   // stage B done reading h -> safe to overwrite

        // ---- prefetch next tile's h (overlaps with stage C + softmax) ----
        if (it + 1 < NT) {
            const int n1 = nb + (it + 1) * R2;
            for (int i = tid; i < 3200; i += TPB2) {
                int r = i / 50, c = i % 50;
                cp16(s2 + O2_H + r * HSTR + c * 4,
                     g_h + (size_t)(n1 + r) * 200 + c * 4);
            }
            if (tid < R2) qn[((it + 1) & 1) * R2 + tid] = questions[n1 + tid];
        }
        asm volatile("cp.async.commit_group;\n" ::: "memory");

        // ---- stage C: W2e(56x100) @ h1 -> feats + logits + mastery ----
        if (tid < 224) {
            int fg = tid >> 3, rg = tid & 7;
            int f0 = fg * 2;
            ull acc[2][8] = {};
            for (int k = 0; k < 100; k += 4) {
                ulonglong2 h1v[8];
#pragma unroll
                for (int i = 0; i < 8; i++)
                    h1v[i] = *(const ulonglong2*)(s2 + O2_H1 + (rg + 8 * i) * H1STR + k);
#pragma unroll
                for (int j = 0; j < 2; j++) {
                    ull w0 = *(const ull*)(s2 + O2_W2E + (f0 + j) * 100 + k);
                    ull w1 = *(const ull*)(s2 + O2_W2E + (f0 + j) * 100 + k + 2);
#pragma unroll
                    for (int i = 0; i < 8; i++) {
                        FMA2(acc[j][i], w0, h1v[i].x, acc[j][i]);
                        FMA2(acc[j][i], w1, h1v[i].y, acc[j][i]);
                    }
                }
            }
#pragma unroll
            for (int j = 0; j < 2; j++) {
                int f = f0 + j;
                if (f >= 55) continue;
                float bias = s2[O2_B2E + f];
#pragma unroll
                for (int i = 0; i < 8; i++) {
                    int row = rg + 8 * i;
                    float val = HADD(acc[j][i]) + bias;
                    if (f < 50)      outF[(size_t)(n0 + row) * 50 + f] = val;
                    else if (f < 54) s2[O2_LG + row * 4 + (f - 50)] = val;
                    else             outM[n0 + row] = val;
                }
            }
        }
        __syncthreads();

        // ---- softmax over logits ----
        {
            int row = tid >> 2, c = tid & 3;
            float lg = s2[O2_LG + row * 4 + c];
            float mx = fmaxf(lg, __shfl_xor_sync(0xffffffffu, lg, 1));
            mx = fmaxf(mx, __shfl_xor_sync(0xffffffffu, mx, 2));
            float e = expf(lg - mx);
            float se = e + __shfl_xor_sync(0xffffffffu, e, 1);
            se += __shfl_xor_sync(0xffffffffu, se, 2);
            size_t o = (size_t)(n0 + row) * 4 + c;
            outL[o] = lg;
            outP[o] = e / se;
        }
    }
}

// ---------------------------------------------------------------------------

extern "C" void kernel_launch(void* const* d_in, const int* in_sizes, int n_in,
                              void* d_out, int out_size) {
    const int*   questions = (const int*)d_in[0];
    const int*   responses = (const int*)d_in[1];
    const float* qet       = (const float*)d_in[2];
    const float* Wv        = (const float*)d_in[3];
    const float* bv        = (const float*)d_in[4];
    const float* km        = (const float*)d_in[5];
    const float* ivm       = (const float*)d_in[6];
    const float* Wq        = (const float*)d_in[7];
    const float* bq        = (const float*)d_in[8];
    const float* Wk        = (const float*)d_in[9];
    const float* bk        = (const float*)d_in[10];
    const float* We        = (const float*)d_in[11];
    const float* be        = (const float*)d_in[12];
    const float* Wa        = (const float*)d_in[13];
    const float* ba        = (const float*)d_in[14];
    const float* W1        = (const float*)d_in[15];
    const float* b1        = (const float*)d_in[16];
    const float* W2        = (const float*)d_in[17];
    const float* b2        = (const float*)d_in[18];
    const float* Wo        = (const float*)d_in[19];
    const float* bo        = (const float*)d_in[20];

    float* out  = (float*)d_out;
    float* outF = out;
    float* outM = out + (size_t)512 * 500 * 50;
    float* outL = outM + (size_t)512 * 500;
    float* outP = outL + (size_t)512 * 500 * 4;

    cudaFuncSetAttribute(phase2, cudaFuncAttributeMaxDynamicSharedMemorySize,
                         P2_SMF * 4);

    prepBF<<<1495, 256>>>(qet, Wq, bq, km, Wk, bk, W1, b1, W2, b2, Wo, bo);
    {
        dim3 grid(63, 7);
        prepC<<<grid, 256>>>(We, be, Wa, ba, Wv, bv);
    }
    phase1<<<512 / G1, TPB1>>>(questions, responses, ivm);
    phase2<<<512 * 500 / (NT * R2), TPB2, P2_SMF * 4>>>(questions,
                                                        outF, outM, outL, outP);
}

// round 16
// speedup vs baseline: 1.1003x; 1.0845x over previous
#include <cuda_runtime.h>
#include <math.h>

typedef unsigned long long ull;
constexpr int S_ = 500;

// ---------------- device scratch ----------------
__device__ float g_at2[1001 * 104];              // duplicated attn pairs
__device__ float g_c1[1001 * 100];
__device__ float g_ea[(size_t)4004 * 400];       // interleaved: [pp]{e0,e1,a0,a1}
__device__ float g_w2e[56 * 100];                // [W2(50); Wo@W2(4); colmean W2(1); 0]
__device__ float g_b2e[56];
__device__ float g_w1p[100 * 200];               // W1[:, :200] packed
__device__ float g_h[(size_t)512 * 500 * 200];   // read vectors

// ---------------- f32x2 helpers ----------------
#define FMA2(d, a, b, c) \
    asm("fma.rn.f32x2 %0, %1, %2, %3;" : "=l"(d) : "l"(a), "l"(b), "l"(c))
__device__ __forceinline__ ull PK(float x, float y) {
    ull u;
    asm("mov.b64 %0, {%1, %2};" : "=l"(u) : "r"(__float_as_uint(x)), "r"(__float_as_uint(y)));
    return u;
}
__device__ __forceinline__ float HADD(ull u) {
    unsigned lo, hi;
    asm("mov.b64 {%0, %1}, %2;" : "=r"(lo), "=r"(hi) : "l"(u));
    return __uint_as_float(lo) + __uint_as_float(hi);
}
__device__ __forceinline__ void cp16(float* dst, const float* src) {
    unsigned d = (unsigned)__cvta_generic_to_shared(dst);
    asm volatile("cp.async.ca.shared.global [%0], [%1], 16;\n" :: "r"(d), "l"(src));
}

// ========== prepAll: attn(+tk) | c1 | fold | w1p | ea-GEMM (fused) ==========
// blocks: [0,1001) attn | [1001,1393) c1 | [1393,1416) fold | [1416,1495) w1p
//         [1495,1936) ea GEMM (441 = 63 x 7 tiles)
__global__ void prepAll(const float* __restrict__ qet, const float* __restrict__ Wq,
                        const float* __restrict__ bq,
                        const float* __restrict__ km, const float* __restrict__ Wk,
                        const float* __restrict__ bk,
                        const float* __restrict__ W1, const float* __restrict__ b1,
                        const float* __restrict__ W2, const float* __restrict__ b2,
                        const float* __restrict__ Wo, const float* __restrict__ bo,
                        const float* __restrict__ We, const float* __restrict__ be,
                        const float* __restrict__ Wa, const float* __restrict__ ba,
                        const float* __restrict__ Wv, const float* __restrict__ bv) {
    __shared__ float stk[2500], qe[50], qu[50], lg[50], red[2];
    __shared__ float As[16][64], Bs[16][64];
    int b = blockIdx.x, tid = threadIdx.x;
    if (b < 1001) {
        int q = b;
        for (int i = tid; i < 2500; i += 256) {
            int m = i / 50, k = i % 50;
            float a = bk[m];
            for (int l = 0; l < 50; l++) a = fmaf(km[l * 50 + k], Wk[m * 50 + l], a);
            stk[i] = a;
        }
        if (tid < 50) qe[tid] = qet[q * 50 + tid];
        __syncthreads();
        if (tid < 50) {
            float a = bq[tid];
            for (int l = 0; l < 50; l++) a = fmaf(Wq[tid * 50 + l], qe[l], a);
            qu[tid] = tanhf(a);
        }
        __syncthreads();
        if (tid < 50) {
            float a = 0.f;
            for (int k = 0; k < 50; k++) a = fmaf(stk[tid * 50 + k], qu[k], a);
            lg[tid] = a;
        }
        __syncthreads();
        if (tid == 0) {
            float mx = -1e30f;
            for (int m = 0; m < 50; m++) mx = fmaxf(mx, lg[m]);
            float s = 0.f;
            for (int m = 0; m < 50; m++) s += expf(lg[m] - mx);
            red[0] = mx; red[1] = 1.f / s;
        }
        __syncthreads();
        if (tid < 52) {
            float v = (tid < 50) ? expf(lg[tid] - red[0]) * red[1] : 0.f;
            g_at2[q * 104 + 2 * tid]     = v;
            g_at2[q * 104 + 2 * tid + 1] = v;
        }
    } else if (b < 1393) {
        int idx = (b - 1001) * 256 + tid;
        if (idx < 1001 * 100) {
            int q = idx / 100, j = idx % 100;
            float a = b1[j];
            const float* w = W1 + j * 250 + 200;
            const float* e = qet + q * 50;
            for (int k = 0; k < 50; k++) a = fmaf(w[k], e[k], a);
            g_c1[idx] = a;
        }
    } else if (b < 1416) {
        int i = (b - 1393) * 256 + tid;
        if (i < 5000) {
            g_w2e[i] = W2[i];
        } else if (i < 5400) {
            int idx = i - 5000, c = idx / 100, k = idx % 100;
            float a = 0.f;
            for (int f = 0; f < 50; f++) a = fmaf(Wo[c * 50 + f], W2[f * 100 + k], a);
            g_w2e[i] = a;
        } else if (i < 5500) {
            int k = i - 5400;
            float a = 0.f;
            for (int f = 0; f < 50; f++) a += W2[f * 100 + k];
            g_w2e[i] = a * (1.f / 50.f);
        } else if (i < 5600) {
            g_w2e[i] = 0.f;
        } else if (i < 5656) {
            int j = i - 5600;
            float v = 0.f;
            if (j < 50) v = b2[j];
            else if (j < 54) {
                int c = j - 50;
                v = bo[c];
                for (int f = 0; f < 50; f++) v = fmaf(Wo[c * 50 + f], b2[f], v);
            } else if (j == 54) {
                float a = 0.f;
                for (int f = 0; f < 50; f++) a += b2[f];
                v = a * (1.f / 50.f);
            }
            g_b2e[j] = v;
        }
    } else if (b < 1495) {
        int i = (b - 1416) * 256 + tid;
        if (i < 100 * 200) {
            int r = i / 200, c = i % 200;
            g_w1p[i] = W1[r * 250 + c];
        }
    } else {
        // ---- erase/add GEMM tile (ve inline), interleaved output layout ----
        int bi = b - 1495;
        int i0 = (bi % 63) * 64, j0 = (bi / 63) * 64;
        int ty = tid >> 4, tx = tid & 15;
        float acc[4][4] = {};
        for (int kb = 0; kb < 200; kb += 16) {
            for (int l = tid; l < 1024; l += 256) {
                {
                    int c = l >> 6, r = l & 63;
                    int gi = i0 + r, gk = kb + c;
                    float val = 0.f;
                    if (gi < 4004 && gk < 200) {
                        int q = gi >> 2, rr = gi & 3;
                        val = bv[gk];
                        if (q > 0) {
#pragma unroll
                            for (int cc = 0; cc < 4; cc++) {
                                float w = 1.0f - fabsf((float)(cc - rr)) * (1.0f / 3.0f);
                                if (w > 0.0f)
                                    val = fmaf(w, Wv[gk * 4000 + cc * 1000 + q - 1], val);
                            }
                        }
                    }
                    As[c][r] = val;
                }
                {
                    int r = l >> 4, c = l & 15;
                    int gj = j0 + r, gk = kb + c;
                    float bval = 0.f;
                    if (gj < 400 && gk < 200)
                        bval = (gj < 200) ? We[gj * 200 + gk] : Wa[(gj - 200) * 200 + gk];
                    Bs[c][r] = bval;
                }
            }
            __syncthreads();
#pragma unroll
            for (int k = 0; k < 16; k++) {
                float a[4], bb[4];
#pragma unroll
                for (int u = 0; u < 4; u++) a[u] = As[k][ty * 4 + u];
#pragma unroll
                for (int u = 0; u < 4; u++) bb[u] = Bs[k][tx * 4 + u];
#pragma unroll
                for (int u = 0; u < 4; u++)
#pragma unroll
                    for (int v = 0; v < 4; v++) acc[u][v] = fmaf(a[u], bb[v], acc[u][v]);
            }
            __syncthreads();
        }
#pragma unroll
        for (int u = 0; u < 4; u++) {
            int gi = i0 + ty * 4 + u;
            if (gi >= 4004) break;
#pragma unroll
            for (int v = 0; v < 4; v++) {
                int gj = j0 + tx * 4 + v;
                if (gj >= 400) continue;
                float x = acc[u][v] + ((gj < 200) ? be[gj] : ba[gj - 200]);
                float val = (gj < 200) ? (1.0f / (1.0f + expf(-x))) : tanhf(x);
                // interleaved layout: pair pp -> {e0, e1, a0, a1}
                int off;
                if (gj < 200) off = 4 * (gj >> 1) + (gj & 1);
                else { int jj = gj - 200; off = 4 * (jj >> 1) + 2 + (jj & 1); }
                g_ea[(size_t)gi * 400 + off] = val;
            }
        }
    }
}

// ======== Phase 1: barrier-free Vm recurrence, G1=4 (R12 + micro-opts) ======
#define TPB1 416
constexpr int G1 = 4;
constexpr int P1_SMF = 4000 + 13 * 416;

__global__ void __launch_bounds__(TPB1, 1)
phase1(const int* __restrict__ questions, const int* __restrict__ responses,
       const float* __restrict__ ivm) {
    __shared__ float sm[P1_SMF];
    int* qs = (int*)sm;
    int* rs = (int*)(sm + 2000);
    const int tid = threadIdx.x;
    const int wid = tid >> 5, lane = tid & 31;
    const int b0 = blockIdx.x * G1;

    for (int i = tid; i < G1 * S_; i += TPB1) {
        qs[i] = questions[b0 * S_ + i];
        rs[i] = responses[b0 * S_ + i];
    }

    const int cp = (tid < 400) ? tid : 399;
    const int g = cp / 100, p = cp % 100;
    const int wg0 = (wid * 32) / 100;
    const int wg1 = min(3, (wid * 32 + 31) / 100);
    const int myslot = (g > wg0) ? 1 : 0;
    const int nchunk = (wg0 == wg1) ? 26 : 52;   // skip unused slot 1

    ull vm[50];
#pragma unroll
    for (int m = 0; m < 50; m++) vm[m] = *(const ull*)(ivm + m * 200 + 2 * p);

    __syncthreads();

    float* mybuf = sm + 4000 + wid * 416;
    const int* qsg = qs + g * S_;
    const int* rsg = rs + g * S_;

    for (int i = lane; i < nchunk; i += 32) {
        int s = i / 26, j = i % 26;
        int qq = qs[(s ? wg1 : wg0) * S_];
        cp16(mybuf + s * 104 + j * 4, g_at2 + qq * 104 + j * 4);
    }
    asm volatile("cp.async.commit_group;\n" ::: "memory");

    ull eC, aC;
    {
        float4 ea4 = *(const float4*)(g_ea + (size_t)(qsg[0] * 4 + rsg[0]) * 400 + 4 * p);
        eC = PK(ea4.x, ea4.y);
        aC = PK(ea4.z, ea4.w);
    }

    size_t hb = (size_t)(b0 + g) * (S_ * 200) + 2 * p;

    for (int t = 0; t < S_; t++) {
        ull eN = 0ull, aN = 0ull;
        if (t + 1 < S_) {
            float4 ea4 = *(const float4*)(g_ea +
                (size_t)(qsg[t + 1] * 4 + rsg[t + 1]) * 400 + 4 * p);
            eN = PK(ea4.x, ea4.y);
            aN = PK(ea4.z, ea4.w);
            float* nb = mybuf + ((t + 1) & 1) * 208;
            for (int i = lane; i < nchunk; i += 32) {
                int s = i / 26, j = i % 26;
                int qq = qs[(s ? wg1 : wg0) * S_ + t + 1];
                cp16(nb + s * 104 + j * 4, g_at2 + qq * 104 + j * 4);
            }
        }
        asm volatile("cp.async.commit_group;\n" ::: "memory");
        asm volatile("cp.async.wait_group 1;\n" ::: "memory");
        __syncwarp();

        const ulonglong2* at2p =
            (const ulonglong2*)(mybuf + (t & 1) * 208 + myslot * 104);
        ull en = eC ^ 0x8000000080000000ULL;
        ull ad = aC;
        ull ra = 0ull, rb = 0ull;
#pragma unroll
        for (int j2 = 0; j2 < 25; j2++) {
            ulonglong2 uu = at2p[j2];
            ull tt;
            FMA2(ra, uu.x, vm[2 * j2], ra);
            FMA2(tt, en, vm[2 * j2], ad);
            FMA2(vm[2 * j2], uu.x, tt, vm[2 * j2]);
            FMA2(rb, uu.y, vm[2 * j2 + 1], rb);
            FMA2(tt, en, vm[2 * j2 + 1], ad);
            FMA2(vm[2 * j2 + 1], uu.y, tt, vm[2 * j2 + 1]);
        }
        ull one2 = PK(1.0f, 1.0f), r2;
        FMA2(r2, rb, one2, ra);
        if (tid < 400)
            *(ull*)(g_h + hb + (size_t)t * 200) = r2;
        eC = eN; aC = aN;
    }
}

// ========= Phase 2: batched MLP, 64 rows/block (R12, frozen) =========
#define TPB2 256
constexpr int R2 = 64;
constexpr int HSTR = 204;
constexpr int H1STR = 108;
constexpr int O2_H   = 0;
constexpr int O2_H1  = 13056;
constexpr int O2_W2E = 19968;
constexpr int O2_B2E = 25568;
constexpr int O2_LG  = 25624;
constexpr int O2_QN  = 25880;
constexpr int P2_SMF = 25944;

__global__ void __launch_bounds__(TPB2, 2)
phase2(const int* __restrict__ questions,
       float* __restrict__ outF, float* __restrict__ outM,
       float* __restrict__ outL, float* __restrict__ outP) {
    extern __shared__ float s2[];
    const int tid = threadIdx.x;
    const int n0 = blockIdx.x * R2;
    int* qn = (int*)(s2 + O2_QN);

    for (int i = tid; i < 3200; i += TPB2) {
        int r = i / 50, c = i % 50;
        cp16(s2 + O2_H + r * HSTR + c * 4, g_h + (size_t)(n0 + r) * 200 + c * 4);
    }
    for (int i = tid; i < 1400; i += TPB2)
        cp16(s2 + O2_W2E + i * 4, g_w2e + i * 4);
    if (tid < 14) cp16(s2 + O2_B2E + tid * 4, g_b2e + tid * 4);
    if (tid < R2) qn[tid] = questions[n0 + tid];
    asm volatile("cp.async.commit_group;\n" ::: "memory");
    asm volatile("cp.async.wait_group 0;\n" ::: "memory");
    __syncthreads();

    if (tid < 200) {
        int jg = tid / 8, rg = tid % 8;
        int j0 = jg * 4;
        ull acc[4][8] = {};
        for (int k = 0; k < 200; k += 4) {
            ulonglong2 h[8];
#pragma unroll
            for (int i = 0; i < 8; i++)
                h[i] = *(const ulonglong2*)(s2 + O2_H + (rg + 8 * i) * HSTR + k);
#pragma unroll
            for (int j = 0; j < 4; j++) {
                ulonglong2 w = *(const ulonglong2*)(g_w1p + (j0 + j) * 200 + k);
#pragma unroll
                for (int i = 0; i < 8; i++) {
                    FMA2(acc[j][i], w.x, h[i].x, acc[j][i]);
                    FMA2(acc[j][i], w.y, h[i].y, acc[j][i]);
                }
            }
        }
#pragma unroll
        for (int j = 0; j < 4; j++)
#pragma unroll
            for (int i = 0; i < 8; i++) {
                int row = rg + 8 * i;
                float v = HADD(acc[j][i]) + g_c1[qn[row] * 100 + j0 + j];
                s2[O2_H1 + row * H1STR + j0 + j] = fmaxf(v, 0.f);
            }
    }
    __syncthreads();

    if (tid < 224) {
        int fg = tid >> 3, rg = tid & 7;
        int f0 = fg * 2;
        ull acc[2][8] = {};
        for (int k = 0; k < 100; k += 4) {
            ulonglong2 h1v[8];
#pragma unroll
            for (int i = 0; i < 8; i++)
                h1v[i] = *(const ulonglong2*)(s2 + O2_H1 + (rg + 8 * i) * H1STR + k);
#pragma unroll
            for (int j = 0; j < 2; j++) {
                ull w0 = *(const ull*)(s2 + O2_W2E + (f0 + j) * 100 + k);
                ull w1 = *(const ull*)(s2 + O2_W2E + (f0 + j) * 100 + k + 2);
#pragma unroll
                for (int i = 0; i < 8; i++) {
                    FMA2(acc[j][i], w0, h1v[i].x, acc[j][i]);
                    FMA2(acc[j][i], w1, h1v[i].y, acc[j][i]);
                }
            }
        }
#pragma unroll
        for (int j = 0; j < 2; j++) {
            int f = f0 + j;
            if (f >= 55) continue;
            float bias = s2[O2_B2E + f];
#pragma unroll
            for (int i = 0; i < 8; i++) {
                int row = rg + 8 * i;
                float val = HADD(acc[j][i]) + bias;
                if (f < 50)      outF[(size_t)(n0 + row) * 50 + f] = val;
                else if (f < 54) s2[O2_LG + row * 4 + (f - 50)] = val;
                else             outM[n0 + row] = val;
            }
        }
    }
    __syncthreads();

    {
        int row = tid >> 2, c = tid & 3;
        float lg = s2[O2_LG + row * 4 + c];
        float mx = fmaxf(lg, __shfl_xor_sync(0xffffffffu, lg, 1));
        mx = fmaxf(mx, __shfl_xor_sync(0xffffffffu, mx, 2));
        float e = expf(lg - mx);
        float se = e + __shfl_xor_sync(0xffffffffu, e, 1);
        se += __shfl_xor_sync(0xffffffffu, se, 2);
        size_t o = (size_t)(n0 + row) * 4 + c;
        outL[o] = lg;
        outP[o] = e / se;
    }
}

// ---------------------------------------------------------------------------

extern "C" void kernel_launch(void* const* d_in, const int* in_sizes, int n_in,
                              void* d_out, int out_size) {
    const int*   questions = (const int*)d_in[0];
    const int*   responses = (const int*)d_in[1];
    const float* qet       = (const float*)d_in[2];
    const float* Wv        = (const float*)d_in[3];
    const float* bv        = (const float*)d_in[4];
    const float* km        = (const float*)d_in[5];
    const float* ivm       = (const float*)d_in[6];
    const float* Wq        = (const float*)d_in[7];
    const float* bq        = (const float*)d_in[8];
    const float* Wk        = (const float*)d_in[9];
    const float* bk        = (const float*)d_in[10];
    const float* We        = (const float*)d_in[11];
    const float* be        = (const float*)d_in[12];
    const float* Wa        = (const float*)d_in[13];
    const float* ba        = (const float*)d_in[14];
    const float* W1        = (const float*)d_in[15];
    const float* b1        = (const float*)d_in[16];
    const float* W2        = (const float*)d_in[17];
    const float* b2        = (const float*)d_in[18];
    const float* Wo        = (const float*)d_in[19];
    const float* bo        = (const float*)d_in[20];

    float* out  = (float*)d_out;
    float* outF = out;
    float* outM = out + (size_t)512 * 500 * 50;
    float* outL = outM + (size_t)512 * 500;
    float* outP = outL + (size_t)512 * 500 * 4;

    cudaFuncSetAttribute(phase2, cudaFuncAttributeMaxDynamicSharedMemorySize,
                         P2_SMF * 4);

    prepAll<<<1936, 256>>>(qet, Wq, bq, km, Wk, bk, W1, b1, W2, b2, Wo, bo,
                           We, be, Wa, ba, Wv, bv);
    phase1<<<512 / G1, TPB1>>>(questions, responses, ivm);
    phase2<<<512 * 500 / R2, TPB2, P2_SMF * 4>>>(questions,
                                                 outF, outM, outL, outP);
}

// round 17
// speedup vs baseline: 1.1651x; 1.0589x over previous
#include <cuda_runtime.h>
#include <math.h>

typedef unsigned long long ull;
constexpr int S_ = 500;

// ---------------- device scratch ----------------
__device__ float g_tk[2500];                     // transformed keys
__device__ float g_at2[1001 * 104];              // duplicated attn pairs
__device__ float g_c1[1001 * 100];
__device__ float g_ea[(size_t)4004 * 400];
__device__ float g_w2e[56 * 100];                // [W2(50); Wo@W2(4); colmean W2(1); 0]
__device__ float g_b2e[56];
__device__ float g_w1p[100 * 200];               // W1[:, :200] packed
__device__ float g_h[(size_t)512 * 500 * 200];   // read vectors

// ---------------- f32x2 helpers ----------------
#define FMA2(d, a, b, c) \
    asm("fma.rn.f32x2 %0, %1, %2, %3;" : "=l"(d) : "l"(a), "l"(b), "l"(c))
__device__ __forceinline__ ull PK(float x, float y) {
    ull u;
    asm("mov.b64 %0, {%1, %2};" : "=l"(u) : "r"(__float_as_uint(x)), "r"(__float_as_uint(y)));
    return u;
}
__device__ __forceinline__ float HADD(ull u) {
    unsigned lo, hi;
    asm("mov.b64 {%0, %1}, %2;" : "=r"(lo), "=r"(hi) : "l"(u));
    return __uint_as_float(lo) + __uint_as_float(hi);
}
__device__ __forceinline__ void cp16(float* dst, const float* src) {
    unsigned d = (unsigned)__cvta_generic_to_shared(dst);
    asm volatile("cp.async.ca.shared.global [%0], [%1], 16;\n" :: "r"(d), "l"(src));
}

// ================= prep0: transformed keys (once) =================
__global__ void prep0(const float* __restrict__ km, const float* __restrict__ Wk,
                      const float* __restrict__ bk) {
    int i = blockIdx.x * 256 + threadIdx.x;
    if (i < 2500) {
        int m = i / 50, k = i % 50;
        float a = bk[m];
        for (int l = 0; l < 50; l++) a = fmaf(km[l * 50 + k], Wk[m * 50 + l], a);
        g_tk[i] = a;
    }
}

// ================= prepBF: attn | c1 | fold | w1 pack =================
__global__ void prepBF(const float* __restrict__ qet, const float* __restrict__ Wq,
                       const float* __restrict__ bq,
                       const float* __restrict__ W1, const float* __restrict__ b1,
                       const float* __restrict__ W2, const float* __restrict__ b2,
                       const float* __restrict__ Wo, const float* __restrict__ bo) {
    __shared__ float qe[50], qu[50], lg[50], red[2];
    int b = blockIdx.x, tid = threadIdx.x;
    if (b < 1001) {
        int q = b;
        if (tid < 50) qe[tid] = qet[q * 50 + tid];
        __syncthreads();
        if (tid < 50) {
            float a = bq[tid];
            for (int l = 0; l < 50; l++) a = fmaf(Wq[tid * 50 + l], qe[l], a);
            qu[tid] = tanhf(a);
        }
        __syncthreads();
        if (tid < 50) {
            float a = 0.f;
            const float* tk = g_tk + tid * 50;
            for (int k = 0; k < 50; k++) a = fmaf(tk[k], qu[k], a);
            lg[tid] = a;
        }
        __syncthreads();
        if (tid == 0) {
            float mx = -1e30f;
            for (int m = 0; m < 50; m++) mx = fmaxf(mx, lg[m]);
            float s = 0.f;
            for (int m = 0; m < 50; m++) s += expf(lg[m] - mx);
            red[0] = mx; red[1] = 1.f / s;
        }
        __syncthreads();
        if (tid < 52) {
            float v = (tid < 50) ? expf(lg[tid] - red[0]) * red[1] : 0.f;
            g_at2[q * 104 + 2 * tid]     = v;
            g_at2[q * 104 + 2 * tid + 1] = v;
        }
    } else if (b < 1393) {
        int idx = (b - 1001) * 256 + tid;
        if (idx < 1001 * 100) {
            int q = idx / 100, j = idx % 100;
            float a = b1[j];
            const float* w = W1 + j * 250 + 200;
            const float* e = qet + q * 50;
            for (int k = 0; k < 50; k++) a = fmaf(w[k], e[k], a);
            g_c1[idx] = a;
        }
    } else if (b < 1416) {
        int i = (b - 1393) * 256 + tid;
        if (i < 5000) {
            g_w2e[i] = W2[i];
        } else if (i < 5400) {
            int idx = i - 5000, c = idx / 100, k = idx % 100;
            float a = 0.f;
            for (int f = 0; f < 50; f++) a = fmaf(Wo[c * 50 + f], W2[f * 100 + k], a);
            g_w2e[i] = a;
        } else if (i < 5500) {
            int k = i - 5400;
            float a = 0.f;
            for (int f = 0; f < 50; f++) a += W2[f * 100 + k];
            g_w2e[i] = a * (1.f / 50.f);
        } else if (i < 5600) {
            g_w2e[i] = 0.f;
        } else if (i < 5656) {
            int j = i - 5600;
            float v = 0.f;
            if (j < 50) v = b2[j];
            else if (j < 54) {
                int c = j - 50;
                v = bo[c];
                for (int f = 0; f < 50; f++) v = fmaf(Wo[c * 50 + f], b2[f], v);
            } else if (j == 54) {
                float a = 0.f;
                for (int f = 0; f < 50; f++) a += b2[f];
                v = a * (1.f / 50.f);
            }
            g_b2e[j] = v;
        }
    } else {
        int i = (b - 1416) * 256 + tid;
        if (i < 100 * 200) {
            int r = i / 200, c = i % 200;
            g_w1p[i] = W1[r * 250 + c];
        }
    }
}

// ================= prepC: erase/add GEMM, ve inline =================
__global__ void prepC(const float* __restrict__ We, const float* __restrict__ be,
                      const float* __restrict__ Wa, const float* __restrict__ ba,
                      const float* __restrict__ Wv, const float* __restrict__ bv) {
    __shared__ float As[16][64];
    __shared__ float Bs[16][64];
    int i0 = blockIdx.x * 64, j0 = blockIdx.y * 64;
    int tid = threadIdx.x;
    int ty = tid >> 4, tx = tid & 15;
    float acc[4][4] = {};
    for (int kb = 0; kb < 200; kb += 16) {
        for (int l = tid; l < 1024; l += 256) {
            {
                int c = l >> 6, r = l & 63;
                int gi = i0 + r, gk = kb + c;
                float val = 0.f;
                if (gi < 4004 && gk < 200) {
                    int q = gi >> 2, rr = gi & 3;
                    val = bv[gk];
                    if (q > 0) {
#pragma unroll
                        for (int cc = 0; cc < 4; cc++) {
                            float w = 1.0f - fabsf((float)(cc - rr)) * (1.0f / 3.0f);
                            if (w > 0.0f)
                                val = fmaf(w, Wv[gk * 4000 + cc * 1000 + q - 1], val);
                        }
                    }
                }
                As[c][r] = val;
            }
            {
                int r = l >> 4, c = l & 15;
                int gj = j0 + r, gk = kb + c;
                float bval = 0.f;
                if (gj < 400 && gk < 200)
                    bval = (gj < 200) ? We[gj * 200 + gk] : Wa[(gj - 200) * 200 + gk];
                Bs[c][r] = bval;
            }
        }
        __syncthreads();
#pragma unroll
        for (int k = 0; k < 16; k++) {
            float a[4], bb[4];
#pragma unroll
            for (int u = 0; u < 4; u++) a[u] = As[k][ty * 4 + u];
#pragma unroll
            for (int u = 0; u < 4; u++) bb[u] = Bs[k][tx * 4 + u];
#pragma unroll
            for (int u = 0; u < 4; u++)
#pragma unroll
                for (int v = 0; v < 4; v++) acc[u][v] = fmaf(a[u], bb[v], acc[u][v]);
        }
        __syncthreads();
    }
#pragma unroll
    for (int u = 0; u < 4; u++) {
        int gi = i0 + ty * 4 + u;
        if (gi >= 4004) break;
#pragma unroll
        for (int v = 0; v < 4; v++) {
            int gj = j0 + tx * 4 + v;
            if (gj >= 400) continue;
            float x = acc[u][v] + ((gj < 200) ? be[gj] : ba[gj - 200]);
            g_ea[(size_t)gi * 400 + gj] = (gj < 200) ? (1.0f / (1.0f + expf(-x))) : tanhf(x);
        }
    }
}

// ======== Phase 1: barrier-free Vm recurrence, G1=4 (R12, frozen) ========
#define TPB1 416
constexpr int G1 = 4;
constexpr int P1_SMF = 4000 + 13 * 416;

__global__ void __launch_bounds__(TPB1, 1)
phase1(const int* __restrict__ questions, const int* __restrict__ responses,
       const float* __restrict__ ivm) {
    __shared__ float sm[P1_SMF];
    int* qs = (int*)sm;
    int* rs = (int*)(sm + 2000);
    const int tid = threadIdx.x;
    const int wid = tid >> 5, lane = tid & 31;
    const int b0 = blockIdx.x * G1;

    for (int i = tid; i < G1 * S_; i += TPB1) {
        qs[i] = questions[b0 * S_ + i];
        rs[i] = responses[b0 * S_ + i];
    }

    const int cp = (tid < 400) ? tid : 399;
    const int g = cp / 100, p = cp % 100;
    const int wg0 = (wid * 32) / 100;
    const int wg1 = min(3, (wid * 32 + 31) / 100);
    const int myslot = (g > wg0) ? 1 : 0;

    ull vm[50];
#pragma unroll
    for (int m = 0; m < 50; m++) vm[m] = *(const ull*)(ivm + m * 200 + 2 * p);

    __syncthreads();

    float* mybuf = sm + 4000 + wid * 416;
    const int* qsg = qs + g * S_;
    const int* rsg = rs + g * S_;

    for (int i = lane; i < 52; i += 32) {
        int s = i / 26, j = i % 26;
        int qq = qs[(s ? wg1 : wg0) * S_];
        cp16(mybuf + s * 104 + j * 4, g_at2 + qq * 104 + j * 4);
    }
    asm volatile("cp.async.commit_group;\n" ::: "memory");

    ull eC, aC;
    {
        const float* eb = g_ea + (size_t)(qsg[0] * 4 + rsg[0]) * 400;
        eC = *(const ull*)(eb + 2 * p);
        aC = *(const ull*)(eb + 200 + 2 * p);
    }

    size_t hb = (size_t)(b0 + g) * (S_ * 200) + 2 * p;

    for (int t = 0; t < S_; t++) {
        ull eN = 0ull, aN = 0ull;
        if (t + 1 < S_) {
            const float* eb = g_ea + (size_t)(qsg[t + 1] * 4 + rsg[t + 1]) * 400;
            eN = *(const ull*)(eb + 2 * p);
            aN = *(const ull*)(eb + 200 + 2 * p);
            float* nb = mybuf + ((t + 1) & 1) * 208;
            for (int i = lane; i < 52; i += 32) {
                int s = i / 26, j = i % 26;
                int qq = qs[(s ? wg1 : wg0) * S_ + t + 1];
                cp16(nb + s * 104 + j * 4, g_at2 + qq * 104 + j * 4);
            }
        }
        asm volatile("cp.async.commit_group;\n" ::: "memory");
        asm volatile("cp.async.wait_group 1;\n" ::: "memory");
        __syncwarp();

        const ulonglong2* at2p =
            (const ulonglong2*)(mybuf + (t & 1) * 208 + myslot * 104);
        ull en = eC ^ 0x8000000080000000ULL;
        ull ad = aC;
        ull ra = 0ull, rb = 0ull;
#pragma unroll
        for (int j2 = 0; j2 < 25; j2++) {
            ulonglong2 uu = at2p[j2];
            ull tt;
            FMA2(ra, uu.x, vm[2 * j2], ra);
            FMA2(tt, en, vm[2 * j2], ad);
            FMA2(vm[2 * j2], uu.x, tt, vm[2 * j2]);
            FMA2(rb, uu.y, vm[2 * j2 + 1], rb);
            FMA2(tt, en, vm[2 * j2 + 1], ad);
            FMA2(vm[2 * j2 + 1], uu.y, tt, vm[2 * j2 + 1]);
        }
        ull one2 = PK(1.0f, 1.0f), r2;
        FMA2(r2, rb, one2, ra);
        if (tid < 400)
            *(ull*)(g_h + hb + (size_t)t * 200) = r2;
        eC = eN; aC = aN;
    }
}

// ========= Phase 2: batched MLP, 64 rows/block (R12, frozen) =========
#define TPB2 256
constexpr int R2 = 64;
constexpr int HSTR = 204;
constexpr int H1STR = 108;
constexpr int O2_H   = 0;
constexpr int O2_H1  = 13056;
constexpr int O2_W2E = 19968;
constexpr int O2_B2E = 25568;
constexpr int O2_LG  = 25624;
constexpr int O2_QN  = 25880;
constexpr int P2_SMF = 25944;

__global__ void __launch_bounds__(TPB2, 2)
phase2(const int* __restrict__ questions,
       float* __restrict__ outF, float* __restrict__ outM,
       float* __restrict__ outL, float* __restrict__ outP) {
    extern __shared__ float s2[];
    const int tid = threadIdx.x;
    const int n0 = blockIdx.x * R2;
    int* qn = (int*)(s2 + O2_QN);

    for (int i = tid; i < 3200; i += TPB2) {
        int r = i / 50, c = i % 50;
        cp16(s2 + O2_H + r * HSTR + c * 4, g_h + (size_t)(n0 + r) * 200 + c * 4);
    }
    for (int i = tid; i < 1400; i += TPB2)
        cp16(s2 + O2_W2E + i * 4, g_w2e + i * 4);
    if (tid < 14) cp16(s2 + O2_B2E + tid * 4, g_b2e + tid * 4);
    if (tid < R2) qn[tid] = questions[n0 + tid];
    asm volatile("cp.async.commit_group;\n" ::: "memory");
    asm volatile("cp.async.wait_group 0;\n" ::: "memory");
    __syncthreads();

    if (tid < 200) {
        int jg = tid / 8, rg = tid % 8;
        int j0 = jg * 4;
        ull acc[4][8] = {};
        for (int k = 0; k < 200; k += 4) {
            ulonglong2 h[8];
#pragma unroll
            for (int i = 0; i < 8; i++)
                h[i] = *(const ulonglong2*)(s2 + O2_H + (rg + 8 * i) * HSTR + k);
#pragma unroll
            for (int j = 0; j < 4; j++) {
                ulonglong2 w = *(const ulonglong2*)(g_w1p + (j0 + j) * 200 + k);
#pragma unroll
                for (int i = 0; i < 8; i++) {
                    FMA2(acc[j][i], w.x, h[i].x, acc[j][i]);
                    FMA2(acc[j][i], w.y, h[i].y, acc[j][i]);
                }
            }
        }
#pragma unroll
        for (int j = 0; j < 4; j++)
#pragma unroll
            for (int i = 0; i < 8; i++) {
                int row = rg + 8 * i;
                float v = HADD(acc[j][i]) + g_c1[qn[row] * 100 + j0 + j];
                s2[O2_H1 + row * H1STR + j0 + j] = fmaxf(v, 0.f);
            }
    }
    __syncthreads();

    if (tid < 224) {
        int fg = tid >> 3, rg = tid & 7;
        int f0 = fg * 2;
        ull acc[2][8] = {};
        for (int k = 0; k < 100; k += 4) {
            ulonglong2 h1v[8];
#pragma unroll
            for (int i = 0; i < 8; i++)
                h1v[i] = *(const ulonglong2*)(s2 + O2_H1 + (rg + 8 * i) * H1STR + k);
#pragma unroll
            for (int j = 0; j < 2; j++) {
                ull w0 = *(const ull*)(s2 + O2_W2E + (f0 + j) * 100 + k);
                ull w1 = *(const ull*)(s2 + O2_W2E + (f0 + j) * 100 + k + 2);
#pragma unroll
                for (int i = 0; i < 8; i++) {
                    FMA2(acc[j][i], w0, h1v[i].x, acc[j][i]);
                    FMA2(acc[j][i], w1, h1v[i].y, acc[j][i]);
                }
            }
        }
#pragma unroll
        for (int j = 0; j < 2; j++) {
            int f = f0 + j;
            if (f >= 55) continue;
            float bias = s2[O2_B2E + f];
#pragma unroll
            for (int i = 0; i < 8; i++) {
                int row = rg + 8 * i;
                float val = HADD(acc[j][i]) + bias;
                if (f < 50)      outF[(size_t)(n0 + row) * 50 + f] = val;
                else if (f < 54) s2[O2_LG + row * 4 + (f - 50)] = val;
                else             outM[n0 + row] = val;
            }
        }
    }
    __syncthreads();

    {
        int row = tid >> 2, c = tid & 3;
        float lg = s2[O2_LG + row * 4 + c];
        float mx = fmaxf(lg, __shfl_xor_sync(0xffffffffu, lg, 1));
        mx = fmaxf(mx, __shfl_xor_sync(0xffffffffu, mx, 2));
        float e = expf(lg - mx);
        float se = e + __shfl_xor_sync(0xffffffffu, e, 1);
        se += __shfl_xor_sync(0xffffffffu, se, 2);
        size_t o = (size_t)(n0 + row) * 4 + c;
        outL[o] = lg;
        outP[o] = e / se;
    }
}

// ---------------------------------------------------------------------------

extern "C" void kernel_launch(void* const* d_in, const int* in_sizes, int n_in,
                              void* d_out, int out_size) {
    const int*   questions = (const int*)d_in[0];
    const int*   responses = (const int*)d_in[1];
    const float* qet       = (const float*)d_in[2];
    const float* Wv        = (const float*)d_in[3];
    const float* bv        = (const float*)d_in[4];
    const float* km        = (const float*)d_in[5];
    const float* ivm       = (const float*)d_in[6];
    const float* Wq        = (const float*)d_in[7];
    const float* bq        = (const float*)d_in[8];
    const float* Wk        = (const float*)d_in[9];
    const float* bk        = (const float*)d_in[10];
    const float* We        = (const float*)d_in[11];
    const float* be        = (const float*)d_in[12];
    const float* Wa        = (const float*)d_in[13];
    const float* ba        = (const float*)d_in[14];
    const float* W1        = (const float*)d_in[15];
    const float* b1        = (const float*)d_in[16];
    const float* W2        = (const float*)d_in[17];
    const float* b2        = (const float*)d_in[18];
    const float* Wo        = (const float*)d_in[19];
    const float* bo        = (const float*)d_in[20];

    float* out  = (float*)d_out;
    float* outF = out;
    float* outM = out + (size_t)512 * 500 * 50;
    float* outL = outM + (size_t)512 * 500;
    float* outP = outL + (size_t)512 * 500 * 4;

    cudaFuncSetAttribute(phase2, cudaFuncAttributeMaxDynamicSharedMemorySize,
                         P2_SMF * 4);

    prep0<<<10, 256>>>(km, Wk, bk);
    prepBF<<<1495, 256>>>(qet, Wq, bq, W1, b1, W2, b2, Wo, bo);
    {
        dim3 grid(63, 7);
        prepC<<<grid, 256>>>(We, be, Wa, ba, Wv, bv);
    }
    phase1<<<512 / G1, TPB1>>>(questions, responses, ivm);
    phase2<<<512 * 500 / R2, TPB2, P2_SMF * 4>>>(questions,
                                                 outF, outM, outL, outP);
}